// round 4
// baseline (speedup 1.0000x reference)
#include <cuda_runtime.h>

// Problem constants
#define T_STEPS 256
#define BATCH   128
#define HID     1024
#define LAT     128
#define PIECE   128

#define NBLK 128   // CTAs: one per 8 hidden units; all co-resident (<=148 SMs)
#define NTHR 128   // threads per CTA
#define KC   32    // k-chunk of h streamed through smem
#define NCHUNK (HID / KC)

typedef unsigned long long ull;

// Persistent state (device globals: no allocation inside kernel_launch)
__device__ float    g_h[2][HID * BATCH];  // h double buffer, layout [k][b]
__device__ unsigned g_bar;                // monotonic grid-barrier counter

// ---------------- helpers ----------------
__device__ __forceinline__ void cp_async16(void* sdst, const void* gsrc) {
    unsigned s = (unsigned)__cvta_generic_to_shared(sdst);
    asm volatile("cp.async.cg.shared.global [%0], [%1], 16;\n" :: "r"(s), "l"(gsrc));
}
__device__ __forceinline__ void cp_commit() { asm volatile("cp.async.commit_group;\n"); }
__device__ __forceinline__ void cp_wait1()  { asm volatile("cp.async.wait_group 1;\n"); }
__device__ __forceinline__ void cp_wait0()  { asm volatile("cp.async.wait_group 0;\n"); }

__device__ __forceinline__ ull pack2(float lo, float hi) {
    ull r; asm("mov.b64 %0, {%1, %2};" : "=l"(r) : "f"(lo), "f"(hi)); return r;
}
__device__ __forceinline__ void unpack2(ull v, float& lo, float& hi) {
    asm("mov.b64 {%0, %1}, %2;" : "=f"(lo), "=f"(hi) : "l"(v));
}
// packed fp32 pair FMA: d.lo += a.lo*b.lo ; d.hi += a.hi*b.hi  (bit-exact per-lane fp32 FMA)
__device__ __forceinline__ void ffma2(ull& d, ull a, ull b) {
    asm("fma.rn.f32x2 %0, %1, %2, %0;" : "+l"(d) : "l"(a), "l"(b));
}
__device__ __forceinline__ float sigf(float x) { return 1.0f / (1.0f + __expf(-x)); }

// Grid barrier: 128 CTAs co-resident (grid <= SM count, 1 CTA/SM).
// EVERY thread fences its own h-stores to L2 before arrival; thread 0 then
// does the release-atomic + spin. Monotonic counter => valid across replays.
__device__ __forceinline__ void grid_bar() {
    __threadfence();
    __syncthreads();
    if (threadIdx.x == 0) {
        unsigned my = atomicAdd(&g_bar, 1u);
        unsigned target = my - (my % NBLK) + NBLK;
        while (*(volatile unsigned*)&g_bar < target) { __nanosleep(40); }
        __threadfence();
    }
    __syncthreads();
}

// ---------------- persistent kernel ----------------
// CTA blk owns hidden units j = blk*8 .. blk*8+7 (all 4 gates each) for ALL batch rows,
// plus FC output column p = blk.
// Thread (ty = tid>>3 in 0..15, tx = tid&7): batch rows ty*8..ty*8+7, hidden unit u = tx.
// Gate column index inside CTA: col = u*4 + gate (gate: 0=i,1=f,2=g,3=o).
extern "C" __global__ void __launch_bounds__(NTHR, 1)
lstm_persistent_kernel(const float* __restrict__ z,
                       const float* __restrict__ w_ih,
                       const float* __restrict__ w_hh,
                       const float* __restrict__ b_ih,
                       const float* __restrict__ b_hh,
                       const float* __restrict__ W_fc,
                       const float* __restrict__ b_fc,
                       float* __restrict__ out)
{
    extern __shared__ float smem[];
    float* Wsm  = smem;                    // [HID][32]  w_hh slice, k-major  (128 KB)
    float* Hst  = Wsm + HID * 32;          // [2][KC*BATCH] h chunk double buf (32 KB)
    float* Xg   = Hst + 2 * KC * BATCH;    // [32][BATCH] step-0 input gates   (16 KB)
    float* wfcs = Xg + 32 * BATCH;         // [HID] W_fc row blk               (4 KB)
    float* bsum = wfcs + HID;              // [32]  b_ih + b_hh slice

    const int tid = threadIdx.x;
    const int blk = blockIdx.x;
    const int tx  = tid & 7;
    const int ty  = tid >> 3;

    // ---------- prologue: load persistent data ----------
    for (int col = 0; col < 32; ++col) {
        int u = col >> 2, g = col & 3;
        int row = g * HID + blk * 8 + u;
        const float* src = w_hh + (size_t)row * HID;
        for (int k = tid; k < HID; k += NTHR)
            Wsm[k * 32 + col] = src[k];
    }
    if (tid < 32) {
        int u = tid >> 2, g = tid & 3;
        int row = g * HID + blk * 8 + u;
        bsum[tid] = b_ih[row] + b_hh[row];
    }
    for (int k = tid; k < HID; k += NTHR) wfcs[k] = W_fc[(size_t)blk * HID + k];
    const float bfc = b_fc[blk];

    // Xg[col][b] = z[b,:] . w_ih[row(col),:]   (input contribution, step 0 only)
    for (int g = 0; g < 4; ++g) {
        int col = tx * 4 + g;
        int row = g * HID + blk * 8 + tx;
        const float* wi = w_ih + (size_t)row * LAT;
        for (int pb = 0; pb < 8; ++pb) {
            int b = ty * 8 + pb;
            const float* zb = z + (size_t)b * LAT;
            float s = 0.f;
            #pragma unroll 4
            for (int l = 0; l < LAT; ++l) s += zb[l] * wi[l];
            Xg[col * BATCH + b] = s;
        }
    }
    __syncthreads();

    // c state lives in registers: index (pair p)*2 + lane  <->  b = ty*8 + 2p + lane
    float cst[8];
    #pragma unroll
    for (int i = 0; i < 8; ++i) cst[i] = 0.f;

    // iterations: t in [0, T]; t>=1 streams h_{t-1} (GEMM for step t + FC for y_{t-1});
    // t<T does the gate epilogue producing h_t; t==T is FC-only for y_{T-1}.
    for (int t = 0; t <= T_STEPS; ++t) {
        ull  acc[4][4];
        float yacc = 0.f;

        if (t >= 1) {
            // init accumulators with gate biases (both packed lanes identical)
            #pragma unroll
            for (int j = 0; j < 4; ++j) {
                float bv = bsum[tx * 4 + j];
                ull bp = pack2(bv, bv);
                #pragma unroll
                for (int p = 0; p < 4; ++p) acc[p][j] = bp;
            }

            const float* hsrc = g_h[t & 1];   // h_{t-1}, layout [k][b]

            // prefetch chunk 0 (cp.async.cg bypasses L1 -> coherent across grid barrier)
            {
                const float4* gs = (const float4*)hsrc;
                float4* sd = (float4*)Hst;
                #pragma unroll
                for (int i = 0; i < 8; ++i)
                    cp_async16(sd + i * NTHR + tid, gs + i * NTHR + tid);
                cp_commit();
            }

            for (int ck = 0; ck < NCHUNK; ++ck) {
                if (ck + 1 < NCHUNK) {
                    const float4* gs = (const float4*)(hsrc + (ck + 1) * KC * BATCH);
                    float4* sd = (float4*)(Hst + ((ck + 1) & 1) * KC * BATCH);
                    #pragma unroll
                    for (int i = 0; i < 8; ++i)
                        cp_async16(sd + i * NTHR + tid, gs + i * NTHR + tid);
                    cp_commit();
                    cp_wait1();
                } else {
                    cp_wait0();
                }
                __syncthreads();

                const float* hb = Hst + (ck & 1) * KC * BATCH;
                const float* wb = Wsm + (size_t)ck * KC * 32;   // <<< FIX: advance weights by chunk

                // GEMM: acc[b-pair][col] += h[k][b] * Wsm[k_glob][col]  via f32x2
                #pragma unroll 8
                for (int k = 0; k < KC; ++k) {
                    float4 w4 = *(const float4*)(wb + k * 32 + tx * 4);
                    ull w2[4] = { pack2(w4.x, w4.x), pack2(w4.y, w4.y),
                                  pack2(w4.z, w4.z), pack2(w4.w, w4.w) };
                    ull h2[4];
                    #pragma unroll
                    for (int p = 0; p < 4; ++p)
                        h2[p] = *(const ull*)(hb + k * BATCH + ty * 8 + p * 2);
                    #pragma unroll
                    for (int p = 0; p < 4; ++p) {
                        #pragma unroll
                        for (int j = 0; j < 4; ++j)
                            ffma2(acc[p][j], h2[p], w2[j]);
                    }
                }

                // FC partial for y_{t-1}: thread tid handles batch row b = tid
                {
                    const float* wf = wfcs + ck * KC;
                    float yp = 0.f;
                    #pragma unroll 8
                    for (int k = 0; k < KC; ++k)
                        yp += hb[k * BATCH + tid] * wf[k];
                    yacc += yp;
                }
                __syncthreads();
            }

            // y_{t-1}[b = tid][p = blk]
            out[(size_t)tid * (T_STEPS * PIECE) + (size_t)(t - 1) * PIECE + blk] = yacc + bfc;
        }

        if (t < T_STEPS) {
            // gate epilogue -> h_t, c_t for this thread's 8 batch rows, unit u = tx
            float hv[8];
            #pragma unroll
            for (int p = 0; p < 4; ++p) {
                float glo[4], ghi[4];
                #pragma unroll
                for (int j = 0; j < 4; ++j) {
                    if (t == 0) {
                        int col = tx * 4 + j;
                        glo[j] = Xg[col * BATCH + ty * 8 + p * 2]     + bsum[col];
                        ghi[j] = Xg[col * BATCH + ty * 8 + p * 2 + 1] + bsum[col];
                    } else {
                        unpack2(acc[p][j], glo[j], ghi[j]);
                    }
                }
                {
                    float i_ = sigf(glo[0]), f_ = sigf(glo[1]);
                    float g_ = tanhf(glo[2]), o_ = sigf(glo[3]);
                    float c = f_ * cst[p * 2] + i_ * g_;
                    cst[p * 2] = c;
                    hv[p * 2] = o_ * tanhf(c);
                }
                {
                    float i_ = sigf(ghi[0]), f_ = sigf(ghi[1]);
                    float g_ = tanhf(ghi[2]), o_ = sigf(ghi[3]);
                    float c = f_ * cst[p * 2 + 1] + i_ * g_;
                    cst[p * 2 + 1] = c;
                    hv[p * 2 + 1] = o_ * tanhf(c);
                }
            }
            // write h_t slice: row j = blk*8 + tx, batch b = ty*8 .. +7 (coalesced float4)
            float* hdst = g_h[(t + 1) & 1] + (size_t)(blk * 8 + tx) * BATCH + ty * 8;
            *(float4*)(hdst)     = make_float4(hv[0], hv[1], hv[2], hv[3]);
            *(float4*)(hdst + 4) = make_float4(hv[4], hv[5], hv[6], hv[7]);

            grid_bar();   // h_t visible to all CTAs before iteration t+1
        }
    }
}

// ---------------- launch ----------------
extern "C" void kernel_launch(void* const* d_in, const int* in_sizes, int n_in,
                              void* d_out, int out_size)
{
    // metadata order: current_batch_size, z, w_ih, w_hh, b_ih, b_hh, W_fc, b_fc
    // (be robust to current_batch_size being omitted)
    int off = (n_in >= 8) ? 1 : 0;
    const float* z    = (const float*)d_in[off + 0];
    const float* w_ih = (const float*)d_in[off + 1];
    const float* w_hh = (const float*)d_in[off + 2];
    const float* b_ih = (const float*)d_in[off + 3];
    const float* b_hh = (const float*)d_in[off + 4];
    const float* W_fc = (const float*)d_in[off + 5];
    const float* b_fc = (const float*)d_in[off + 6];

    const int smem_bytes = (HID * 32 + 2 * KC * BATCH + 32 * BATCH + HID + 32) * (int)sizeof(float);
    cudaFuncSetAttribute(lstm_persistent_kernel,
                         cudaFuncAttributeMaxDynamicSharedMemorySize, smem_bytes);

    lstm_persistent_kernel<<<NBLK, NTHR, smem_bytes>>>(
        z, w_ih, w_hh, b_ih, b_hh, W_fc, b_fc, (float*)d_out);
}